// round 16
// baseline (speedup 1.0000x reference)
#include <cuda_runtime.h>
#include <math.h>
#include <stdint.h>

// Problem constants: B=64, S=2048, I=256, H=256, G=2H=512
#define BATCH 64
#define SEQ   2048
#define HID   256
#define GATES 512
#define WROWS 272          // rows in global transposed weights (>=256 zero)

// -------- scratch (static device arrays; no allocation) --------
__device__ float g_gx[67108864];          // (B*S, 512) fp32 = 256 MB
__device__ float g_WhT0[WROWS * GATES];   // [j][g]
__device__ float g_WiT1[WROWS * GATES];
__device__ float g_WhT1[WROWS * GATES];

// ---------------------------------------------------------------
// Kernel 0: transpose weights into [j][g] layout.
// ---------------------------------------------------------------
__global__ void prep_kernel(const float* __restrict__ Wh0,
                            const float* __restrict__ Wi1,
                            const float* __restrict__ Wh1)
{
    int idx = blockIdx.x * 256 + threadIdx.x;
    const int perp = WROWS * GATES;
    if (idx < 3 * perp) {
        int m = idx / perp;
        int e = idx - m * perp;
        int j = e >> 9;
        int g = e & 511;
        const float* src = (m == 0) ? Wh0 : (m == 1) ? Wi1 : Wh1;
        float*       dst = (m == 0) ? g_WhT0 : (m == 1) ? g_WiT1 : g_WhT1;
        dst[e] = (j < HID) ? src[g * HID + j] : 0.0f;
    }
}

// ---------------------------------------------------------------
// Kernel 1: gx0 = (x @ Wi0^T + bi0) + bh0   (unchanged — passing)
// ---------------------------------------------------------------
__global__ void __launch_bounds__(256, 2)
gemm_gx_kernel(const float* __restrict__ x,
               const float* __restrict__ Wi0,
               const float* __restrict__ bi0,
               const float* __restrict__ bh0)
{
    __shared__ float As[32][68];
    __shared__ float Bs[32][68];

    const int m0  = blockIdx.x * 64;
    const int n0  = blockIdx.y * 64;
    const int tid = threadIdx.x;
    const int tx  = tid & 15;
    const int ty  = tid >> 4;

    float acc[4][4];
#pragma unroll
    for (int i = 0; i < 4; i++)
#pragma unroll
        for (int j = 0; j < 4; j++) acc[i][j] = 0.f;

    for (int k0 = 0; k0 < 256; k0 += 32) {
#pragma unroll
        for (int v = 0; v < 2; v++) {
            int idx = tid + v * 256;
            int r   = idx >> 3;
            int kk  = (idx & 7) << 2;
            float4 av = *reinterpret_cast<const float4*>(
                x + (size_t)(m0 + r) * 256 + (k0 + kk));
            As[kk + 0][r] = av.x; As[kk + 1][r] = av.y;
            As[kk + 2][r] = av.z; As[kk + 3][r] = av.w;
            float4 bv = *reinterpret_cast<const float4*>(
                Wi0 + (size_t)(n0 + r) * 256 + (k0 + kk));
            Bs[kk + 0][r] = bv.x; Bs[kk + 1][r] = bv.y;
            Bs[kk + 2][r] = bv.z; Bs[kk + 3][r] = bv.w;
        }
        __syncthreads();
#pragma unroll
        for (int k = 0; k < 32; k++) {
            float4 av = *reinterpret_cast<const float4*>(&As[k][ty << 2]);
            float4 bv = *reinterpret_cast<const float4*>(&Bs[k][tx << 2]);
            float aa[4] = {av.x, av.y, av.z, av.w};
            float bb[4] = {bv.x, bv.y, bv.z, bv.w};
#pragma unroll
            for (int i = 0; i < 4; i++)
#pragma unroll
                for (int j = 0; j < 4; j++)
                    acc[i][j] = __fmaf_rn(aa[i], bb[j], acc[i][j]);
        }
        __syncthreads();
    }

    float4 b1 = *reinterpret_cast<const float4*>(bi0 + n0 + (tx << 2));
    float4 b2 = *reinterpret_cast<const float4*>(bh0 + n0 + (tx << 2));

#pragma unroll
    for (int i = 0; i < 4; i++) {
        int r = m0 + (ty << 2) + i;
        float4 o;
        o.x = __fadd_rn(__fadd_rn(acc[i][0], b1.x), b2.x);
        o.y = __fadd_rn(__fadd_rn(acc[i][1], b1.y), b2.y);
        o.z = __fadd_rn(__fadd_rn(acc[i][2], b1.z), b2.z);
        o.w = __fadd_rn(__fadd_rn(acc[i][3], b1.w), b2.w);
        *reinterpret_cast<float4*>(g_gx + (size_t)r * GATES + n0 + (tx << 2)) = o;
    }
}

// ---------------------------------------------------------------
// Cluster helpers (8-CTA clusters)
// ---------------------------------------------------------------
__device__ __forceinline__ unsigned ctarank()
{
    unsigned r;
    asm("mov.u32 %0, %%cluster_ctarank;" : "=r"(r));
    return r;
}

// startup/shutdown ONLY (barrier.cluster emits CCTL.IVALL -> L1D flush)
#define CLUSTER_SYNC() do {                                            \
    asm volatile("barrier.cluster.arrive.aligned;" ::: "memory");      \
    asm volatile("barrier.cluster.wait.aligned;"   ::: "memory");      \
} while (0)

__device__ __forceinline__ void remote_st_u64(const volatile void* lptr, int rank,
                                              unsigned long long val)
{
    unsigned laddr;
    asm("{ .reg .u64 t; cvta.to.shared.u64 t, %1; cvt.u32.u64 %0, t; }"
        : "=r"(laddr) : "l"(lptr));
    unsigned raddr;
    asm volatile("mapa.shared::cluster.u32 %0, %1, %2;"
                 : "=r"(raddr) : "r"(laddr), "r"(rank));
    asm volatile("st.shared::cluster.u64 [%0], %1;"
                 :: "r"(raddr), "l"(val) : "memory");
}

__device__ __forceinline__ unsigned poll_mask(
    const volatile unsigned long long* p, unsigned tag)
{
    unsigned long long v = *p;
    while ((unsigned)(v >> 32) != tag) v = *p;
    return (unsigned)v;
}

// XLA logistic: 1/(1+exp(-x)), exp via fp64 rounded to f32 (passing numerics).
__device__ __forceinline__ float sigmoid_ref(float g)
{
    float ef = (float)exp(-(double)g);
    return __fdiv_rn(1.0f, __fadd_rn(1.0f, ef));
}

// predicated packed add: if (bit) { a01 += w01; a23 += w23; } (each lane is
// two independent rn f32 adds — exact chain skip when bit==0)
#define PADD2X2(a01, a23, w01, w23, bit)                                 \
    asm volatile("{ .reg .pred p; setp.ne.u32 p, %4, 0;\n\t"             \
                 "@p add.rn.f32x2 %0, %0, %2;\n\t"                       \
                 "@p add.rn.f32x2 %1, %1, %3; }"                         \
                 : "+l"(a01), "+l"(a23)                                  \
                 : "l"(w01), "l"(w23), "r"(bit))

// ---------------------------------------------------------------
// Kernel 2: spiking-LSTM scan, dense mask-predicated matvecs with
// 4-batch weight-row sharing. 16 clusters x 8 CTAs = 128 CTAs.
// CTA rank r owns units [32r,32r+32) -> 64 gate cols; per-CTA weight
// footprint 3*256*256B = 192 KB (L1-resident; no per-step L1 flush).
// Depth-2 pipeline; all roles run concurrently; ONE syncthreads/step.
//   warps 0-3 : L0(t) update (batch q=warp)     [reads m0s[(t+1)&1], gxs[t&1]]
//   warps 4-7 : L1(t-1) update (batch q=warp-4) [reads g1s/mhs[(t+1)&1]]
//   warps 8-13: dense matvecs Wi1/Wh0/Wh1 (x2 col-halves, 4 batches/lane-grp)
//               [poll tagged masks; write buffers t&1]
//   warps 14-15: gx prefetch for t+1 -> gxs[(t+1)&1]
// ---------------------------------------------------------------
__global__ void __launch_bounds__(512, 1) __cluster_dims__(8, 1, 1)
recurrent8(const float* __restrict__ bi1,
           const float* __restrict__ bh1,
           float* __restrict__ out)
{
    const int tid  = threadIdx.x;
    const int lane = tid & 31;
    const int warp = tid >> 5;
    const int rank = (int)ctarank();
    const int b0   = (blockIdx.x >> 3) * 4;     // first batch of this cluster

    __shared__ float gxs[2][256];               // [buf][q*64+k]
    __shared__ float m0s[2][256];               // Wh0 . h0
    __shared__ float mhs[2][256];               // Wh1 . h1
    __shared__ float g1s[2][256];               // (Wi1.h0 + bi1) + bh1
    __shared__ float c0s[128], c1s[128];        // [q*32+u]
    __shared__ volatile unsigned long long mail0[2][32], mail1[2][32];

    if (tid < 256) {
        m0s[0][tid] = 0.f; m0s[1][tid] = 0.f;
        mhs[0][tid] = 0.f; mhs[1][tid] = 0.f;
        g1s[0][tid] = 0.f; g1s[1][tid] = 0.f;
    }
    if (tid < 128) { c0s[tid] = 0.f; c1s[tid] = 0.f; }
    if (tid < 32) {
        mail0[0][tid] = 0ULL; mail0[1][tid] = 0ULL;  // tag0 (first m0 tag is 1)
        mail1[0][tid] = 0ULL; mail1[1][tid] = 0ULL;  // tag0 mask0 = initial h1=0
    }

    // matvec per-lane constants
    const int wi   = warp - 8;                  // matvec warp index 0..5
    const int mat  = wi >> 1;                   // 0=Wi1, 1=Wh0, 2=Wh1
    const int half = wi & 1;
    const int bq   = lane >> 3;                 // batch 0..3
    const int kq   = half * 8 + (lane & 7);     // col-quad 0..15
    const int gc   = (kq < 8) ? (32 * rank + 4 * kq)
                              : (256 + 32 * rank + 4 * (kq - 8));
    float4 bi1v = make_float4(0.f, 0.f, 0.f, 0.f), bh1v = bi1v;
    if (warp >= 8 && warp < 10) {               // Wi1 warps need biases
        bi1v = *reinterpret_cast<const float4*>(bi1 + gc);
        bh1v = *reinterpret_cast<const float4*>(bh1 + gc);
    }

    // gx preload for t=0 into buffer 0
    if (tid >= 448) {
        int k = tid - 448;                      // 0..63 local col
        int gcol = (k < 32) ? (32 * rank + k) : (256 + 32 * rank + (k - 32));
#pragma unroll
        for (int q = 0; q < 4; q++)
            gxs[0][q * 64 + k] =
                __ldcg(g_gx + (size_t)(b0 + q) * ((size_t)SEQ * GATES) + gcol);
    }
    __syncthreads();
    CLUSTER_SYNC();     // peer smem (mailboxes) initialized before exchanges

    for (int t = 0; t < SEQ; ++t) {
        const int wb = t & 1;                   // matvec write buffer
        const int rb = (t + 1) & 1;             // update read buffer

        if (warp < 4) {
            // ---- L0(t) update: batch q=warp, unit u=lane ----
            const int q = warp, u = lane;
            float g  = __fadd_rn(gxs[wb][q * 64 + u],      m0s[rb][q * 64 + u]);
            float ct = __fadd_rn(gxs[wb][q * 64 + 32 + u], m0s[rb][q * 64 + 32 + u]);
            float f  = sigmoid_ref(g);
            float cc = __fadd_rn(__fmul_rn(f, c0s[q * 32 + u]),
                                 __fmul_rn(__fsub_rn(1.0f, f), ct));
            c0s[q * 32 + u] = cc;
            unsigned bal = __ballot_sync(0xffffffffu, cc > 0.f);
            unsigned long long val =
                ((unsigned long long)(unsigned)(t + 1) << 32) | bal;
            if (lane < 8)
                remote_st_u64(&mail0[(t + 1) & 1][q * 8 + rank], lane, val);
        } else if (warp < 8) {
            // ---- L1(t-1) update: batch q=warp-4 ----
            if (t > 0) {
                const int q = warp - 4, u = lane;
                float g  = __fadd_rn(g1s[rb][q * 64 + u],      mhs[rb][q * 64 + u]);
                float ct = __fadd_rn(g1s[rb][q * 64 + 32 + u], mhs[rb][q * 64 + 32 + u]);
                float f  = sigmoid_ref(g);
                float cc = __fadd_rn(__fmul_rn(f, c1s[q * 32 + u]),
                                     __fmul_rn(__fsub_rn(1.0f, f), ct));
                c1s[q * 32 + u] = cc;
                out[((size_t)(b0 + q) * SEQ + (t - 1)) * HID + (32 * rank + u)] =
                    (cc > 0.f) ? 1.f : 0.f;
                unsigned bal = __ballot_sync(0xffffffffu, cc > 0.f);
                unsigned long long val =
                    ((unsigned long long)(unsigned)t << 32) | bal;
                if (lane < 8)
                    remote_st_u64(&mail1[t & 1][q * 8 + rank], lane, val);
            }
        } else if (warp < 14) {
            // ---- dense matvec: 4 batches share each weight-row load ----
            const unsigned tg = (mat < 2) ? (unsigned)(t + 1) : (unsigned)t;
            const volatile unsigned long long* MB =
                (mat < 2) ? &mail0[tg & 1][0] : &mail1[tg & 1][0];
            unsigned pv = poll_mask(&MB[lane], tg);   // lane -> (q=lane>>3, r=lane&7)
            unsigned m[8];
#pragma unroll
            for (int r = 0; r < 8; r++)
                m[r] = __shfl_sync(0xffffffffu, pv, (bq << 3) | r);

            const float* W = (mat == 0) ? g_WiT1 : (mat == 1) ? g_WhT0 : g_WhT1;
            const float* Wc = W + gc;
            unsigned long long a01 = 0ULL, a23 = 0ULL;
            for (int blk = 0; blk < 8; blk++) {
                unsigned mw = m[blk];
                const ulonglong2* rp = reinterpret_cast<const ulonglong2*>(
                    Wc + (size_t)(blk * 32) * GATES);
#pragma unroll
                for (int r = 0; r < 32; r++) {
                    ulonglong2 wv = rp[(size_t)r * (GATES / 4)];
                    unsigned bit = mw & 1u;
                    mw >>= 1;
                    PADD2X2(a01, a23, wv.x, wv.y, bit);
                }
            }
            float f0, f1, f2, f3;
            asm("mov.b64 {%0, %1}, %2;" : "=f"(f0), "=f"(f1) : "l"(a01));
            asm("mov.b64 {%0, %1}, %2;" : "=f"(f2), "=f"(f3) : "l"(a23));
            const int kb = bq * 64 + 4 * kq;    // smem slot [q][localcol]
            if (mat == 0) {
                float4 gi;
                gi.x = __fadd_rn(__fadd_rn(f0, bi1v.x), bh1v.x);
                gi.y = __fadd_rn(__fadd_rn(f1, bi1v.y), bh1v.y);
                gi.z = __fadd_rn(__fadd_rn(f2, bi1v.z), bh1v.z);
                gi.w = __fadd_rn(__fadd_rn(f3, bi1v.w), bh1v.w);
                *reinterpret_cast<float4*>(&g1s[wb][kb]) = gi;
            } else if (mat == 1) {
                *reinterpret_cast<float4*>(&m0s[wb][kb]) = make_float4(f0, f1, f2, f3);
            } else {
                *reinterpret_cast<float4*>(&mhs[wb][kb]) = make_float4(f0, f1, f2, f3);
            }
        } else {
            // ---- gx prefetch for t+1 ----
            int tn = t + 1;
            if (tn < SEQ) {
                int k = tid - 448;
                int gcol = (k < 32) ? (32 * rank + k)
                                    : (256 + 32 * rank + (k - 32));
#pragma unroll
                for (int q = 0; q < 4; q++)
                    gxs[(tn & 1)][q * 64 + k] =
                        __ldcg(g_gx + (size_t)(b0 + q) * ((size_t)SEQ * GATES)
                               + (size_t)tn * GATES + gcol);
            }
        }
        __syncthreads();
    }

    // -------- epilogue: L1 update for step SEQ-1 (buffers parity 1) ------
    if (tid < 128) {
        const int q = tid >> 5, u = tid & 31;
        float g  = __fadd_rn(g1s[1][q * 64 + u],      mhs[1][q * 64 + u]);
        float ct = __fadd_rn(g1s[1][q * 64 + 32 + u], mhs[1][q * 64 + 32 + u]);
        float f  = sigmoid_ref(g);
        float cc = __fadd_rn(__fmul_rn(f, c1s[q * 32 + u]),
                             __fmul_rn(__fsub_rn(1.0f, f), ct));
        out[((size_t)(b0 + q) * SEQ + (SEQ - 1)) * HID + (32 * rank + u)] =
            (cc > 0.f) ? 1.f : 0.f;

        // finals: h_n (2,B,H) then c_n (2,B,H)
        const size_t HN = (size_t)BATCH * SEQ * HID;
        const size_t CN = HN + (size_t)2 * BATCH * HID;
        const int bb = b0 + q;
        const int ui = 32 * rank + u;
        float cc0 = c0s[q * 32 + u];
        out[HN + ((size_t)0 * BATCH + bb) * HID + ui] = (cc0 > 0.f) ? 1.f : 0.f;
        out[HN + ((size_t)1 * BATCH + bb) * HID + ui] = (cc  > 0.f) ? 1.f : 0.f;
        out[CN + ((size_t)0 * BATCH + bb) * HID + ui] = cc0;
        out[CN + ((size_t)1 * BATCH + bb) * HID + ui] = cc;
    }

    CLUSTER_SYNC();    // shutdown: peer DSMEM stores may be in flight
}

// ---------------------------------------------------------------
extern "C" void kernel_launch(void* const* d_in, const int* in_sizes, int n_in,
                              void* d_out, int out_size)
{
    const float* x   = (const float*)d_in[0];
    const float* Wi0 = (const float*)d_in[1];
    const float* bi0 = (const float*)d_in[2];
    const float* Wh0 = (const float*)d_in[3];
    const float* bh0 = (const float*)d_in[4];
    const float* Wi1 = (const float*)d_in[5];
    const float* bi1 = (const float*)d_in[6];
    const float* Wh1 = (const float*)d_in[7];
    const float* bh1 = (const float*)d_in[8];
    float* out = (float*)d_out;

    prep_kernel<<<1632, 256>>>(Wh0, Wi1, Wh1);

    dim3 gg(2048, 8);
    gemm_gx_kernel<<<gg, 256>>>(x, Wi0, bi0, bh0);

    // 16 clusters x 8 CTAs = 128 CTAs; cluster handles 4 batch elements
    recurrent8<<<128, 512>>>(bi1, bh1, out);
}